// round 4
// baseline (speedup 1.0000x reference)
#include <cuda_runtime.h>
#include <cstdint>

#define NCELLS_TOTAL 802816              // 16384 * 49
#define CELLS_PER_TILE 128
#define NTHREADS 256
#define NTILES (NCELLS_TOTAL / CELLS_PER_TILE)   // 6272
#define GRID 444                                  // 148 SMs * 3 blocks, persistent
#define ELE 30
#define F4_PER_TENSOR (CELLS_PER_TILE * ELE / 4)  // 960
#define TILE_FLOATS (CELLS_PER_TILE * ELE)        // 3840
#define BUF_FLOATS (2 * TILE_FLOATS)              // 7680 floats per stage (p + t)

__device__ float g_partials[GRID];
__device__ unsigned int g_count = 0;

__device__ __forceinline__ float iou_fn(const float* bp, const float* bt) {
    float px1 = bp[0] - bp[2] * 0.5f, py1 = bp[1] - bp[3] * 0.5f;
    float px2 = bp[0] + bp[2] * 0.5f, py2 = bp[1] + bp[3] * 0.5f;
    float tx1 = bt[0] - bt[2] * 0.5f, ty1 = bt[1] - bt[3] * 0.5f;
    float tx2 = bt[0] + bt[2] * 0.5f, ty2 = bt[1] + bt[3] * 0.5f;
    float lx = fmaxf(px1, tx1), ly = fmaxf(py1, ty1);
    float rx = fminf(px2, tx2), ry = fminf(py2, ty2);
    float w = fmaxf(rx - lx, 0.0f);
    float h = fmaxf(ry - ly, 0.0f);
    float inter = w * h;
    float ap = (px2 - px1) * (py2 - py1);
    float at = (tx2 - tx1) * (ty2 - ty1);
    return inter / (ap + at - inter + 1e-10f);
}

__device__ __forceinline__ float block_reduce(float v, float* wsum) {
    const int tid = threadIdx.x;
    #pragma unroll
    for (int o = 16; o > 0; o >>= 1)
        v += __shfl_xor_sync(0xFFFFFFFFu, v, o);
    if ((tid & 31) == 0) wsum[tid >> 5] = v;
    __syncthreads();
    v = 0.0f;
    if (tid < 32) {
        v = (tid < NTHREADS / 32) ? wsum[tid] : 0.0f;
        #pragma unroll
        for (int o = 4; o > 0; o >>= 1)
            v += __shfl_xor_sync(0xFFFFFFFFu, v, o);
    }
    return v;  // valid in tid 0
}

// Issue async copy of one tile (p + t) into `buf`, then commit a group.
// Always commits (even past the end) so group counts stay uniform.
__device__ __forceinline__ void prefetch_tile(int tile, float* buf,
                                              const float4* __restrict__ p4,
                                              const float4* __restrict__ t4,
                                              int tid) {
    if (tile < NTILES) {
        const int base = tile * F4_PER_TENSOR;
        uint32_t sP = (uint32_t)__cvta_generic_to_shared(buf);
        uint32_t sT = sP + TILE_FLOATS * 4;
        #pragma unroll
        for (int k = 0; k < 4; k++) {
            int i = tid + k * NTHREADS;
            if (i < F4_PER_TENSOR) {
                asm volatile("cp.async.cg.shared.global [%0], [%1], 16;"
                             :: "r"(sP + i * 16), "l"(p4 + base + i));
                asm volatile("cp.async.cg.shared.global [%0], [%1], 16;"
                             :: "r"(sT + i * 16), "l"(t4 + base + i));
            }
        }
    }
    asm volatile("cp.async.commit_group;");
}

__global__ __launch_bounds__(NTHREADS)
void yolo_loss_kernel(const float* __restrict__ predict,
                      const float* __restrict__ target,
                      float* __restrict__ out, int out_size) {
    extern __shared__ float smem[];   // [2 * BUF_FLOATS]
    __shared__ float wsum[NTHREADS / 32];
    __shared__ int s_is_last;

    const int tid = threadIdx.x;
    const float4* p4 = (const float4*)predict;
    const float4* t4 = (const float4*)target;

    float acc = 0.0f;

    // Prologue: prefetch first tile into stage 0
    prefetch_tile(blockIdx.x, smem, p4, t4, tid);

    int parity = 0;
    for (int tile = blockIdx.x; tile < NTILES; tile += GRID) {
        // Prefetch next tile into the other stage (safe: barrier at end of prev iter)
        prefetch_tile(tile + GRID, smem + (parity ^ 1) * BUF_FLOATS, p4, t4, tid);

        // Wait until the current tile's group is complete (<=1 pending)
        asm volatile("cp.async.wait_group 1;");
        __syncthreads();

        const float* bp = smem + parity * BUF_FLOATS;
        const float* bt = bp + TILE_FLOATS;

        if (tid < CELLS_PER_TILE) {
            // ---- box half: elements 0..9 of one cell ----
            const float2* P2 = (const float2*)(bp + tid * ELE);
            const float2* T2 = (const float2*)(bt + tid * ELE);
            float p[10], t[10];
            #pragma unroll
            for (int j = 0; j < 5; j++) {
                float2 a = P2[j]; p[2 * j] = a.x; p[2 * j + 1] = a.y;
                float2 b = T2[j]; t[2 * j] = b.x; t[2 * j + 1] = b.y;
            }

            float conf_flag = t[5];
            float coord = (conf_flag > 0.0f) ? 1.0f : 0.0f;
            float noobj = (conf_flag == 0.0f) ? 1.0f : 0.0f;

            float d4a = p[4] - t[4];
            float d4b = p[9] - t[9];
            float noobj_conf = noobj * (d4a * d4a + d4b * d4b);

            float iou00 = iou_fn(p,     t);
            float iou01 = iou_fn(p,     t + 5);
            float iou10 = iou_fn(p + 5, t);
            float iou11 = iou_fn(p + 5, t + 5);

            int bi0 = (iou10 > iou00) ? 1 : 0;   // ties -> 0, matches jnp.argmax
            int bi1 = (iou11 > iou01) ? 1 : 0;
            float best0 = (bi0 == 0 || bi1 == 0) ? 1.0f : 0.0f;
            float best1 = (bi0 == 1 || bi1 == 1) ? 1.0f : 0.0f;
            float resp0 = coord * best0;
            float resp1 = coord * best1;

            float conf_loss = resp0 * d4a * d4a + resp1 * d4b * d4b;

            float c0 = p[0] - t[0], c1 = p[1] - t[1];
            float c5 = p[5] - t[5], c6 = p[6] - t[6];
            float center = resp0 * (c0 * c0 + c1 * c1) + resp1 * (c5 * c5 + c6 * c6);

            float w0 = p[2] - t[2], h0 = p[3] - t[3];
            float w1 = p[7] - t[7], h1 = p[8] - t[8];
            float wh = resp0 * (w0 * w0 + h0 * h0) + resp1 * (w1 * w1 + h1 * h1);

            acc += 5.0f * (center + wh) + conf_loss + 0.5f * noobj_conf;
        } else {
            // ---- class half: elements 10..29 of one cell ----
            const int cell = tid - CELLS_PER_TILE;
            const float* base_p = bp + cell * ELE;
            const float* base_t = bt + cell * ELE;
            float conf_flag = base_t[5];
            float coord = (conf_flag > 0.0f) ? 1.0f : 0.0f;

            const float2* P2 = (const float2*)(base_p + 10);
            const float2* T2 = (const float2*)(base_t + 10);
            float cls = 0.0f;
            #pragma unroll
            for (int j = 0; j < 10; j++) {
                float2 a = P2[j];
                float2 b = T2[j];
                float dx = a.x - b.x;
                float dy = a.y - b.y;
                cls += dx * dx + dy * dy;
            }
            acc += coord * cls;
        }

        __syncthreads();   // all reads of this stage done before it's overwritten
        parity ^= 1;
    }

    // Per-block deterministic reduction, then last-block final sum
    __syncthreads();
    float bsum = block_reduce(acc, wsum);
    if (tid == 0) {
        g_partials[blockIdx.x] = bsum;
        __threadfence();
        unsigned int prev = atomicAdd(&g_count, 1u);
        s_is_last = (prev == GRID - 1) ? 1 : 0;
    }
    __syncthreads();

    if (s_is_last) {
        __threadfence();
        float s = g_partials[tid];
        if (tid + NTHREADS < GRID) s += g_partials[tid + NTHREADS];
        __syncthreads();
        float tot = block_reduce(s, wsum);
        if (tid == 0) {
            out[0] = tot;
            g_count = 0;   // reset for next graph replay
        }
        for (int i = tid + 1; i < out_size; i += NTHREADS) out[i] = 0.0f;
    }
}

extern "C" void kernel_launch(void* const* d_in, const int* in_sizes, int n_in,
                              void* d_out, int out_size) {
    const float* predict = (const float*)d_in[0];
    const float* target  = (const float*)d_in[1];
    float* out = (float*)d_out;

    size_t smem = (size_t)2 * BUF_FLOATS * sizeof(float);   // 61440 B
    cudaFuncSetAttribute(yolo_loss_kernel,
                         cudaFuncAttributeMaxDynamicSharedMemorySize, (int)smem);

    yolo_loss_kernel<<<GRID, NTHREADS, smem>>>(predict, target, out, out_size);
}

// round 5
// speedup vs baseline: 1.1706x; 1.1706x over previous
#include <cuda_runtime.h>
#include <cstdint>

#define NCELLS_TOTAL 802816              // 16384 * 49
#define CELLS_PER_TILE 128
#define NTHREADS 256
#define NTILES (NCELLS_TOTAL / CELLS_PER_TILE)   // 6272
#define GRID 296                                  // 148 SMs * 2 blocks, persistent
#define ELE 30
#define TILE_FLOATS (CELLS_PER_TILE * ELE)        // 3840
#define TILE_BYTES (TILE_FLOATS * 4)              // 15360 per tensor
#define STAGE_FLOATS (2 * TILE_FLOATS)            // 7680 (p + t)
#define STAGE_BYTES (STAGE_FLOATS * 4)            // 30720
#define NSTAGES 3

__device__ float g_partials[GRID];
__device__ unsigned int g_count = 0;

__device__ __forceinline__ float iou_fn(const float* bp, const float* bt) {
    float px1 = bp[0] - bp[2] * 0.5f, py1 = bp[1] - bp[3] * 0.5f;
    float px2 = bp[0] + bp[2] * 0.5f, py2 = bp[1] + bp[3] * 0.5f;
    float tx1 = bt[0] - bt[2] * 0.5f, ty1 = bt[1] - bt[3] * 0.5f;
    float tx2 = bt[0] + bt[2] * 0.5f, ty2 = bt[1] + bt[3] * 0.5f;
    float lx = fmaxf(px1, tx1), ly = fmaxf(py1, ty1);
    float rx = fminf(px2, tx2), ry = fminf(py2, ty2);
    float w = fmaxf(rx - lx, 0.0f);
    float h = fmaxf(ry - ly, 0.0f);
    float inter = w * h;
    float ap = (px2 - px1) * (py2 - py1);
    float at = (tx2 - tx1) * (ty2 - ty1);
    return inter / (ap + at - inter + 1e-10f);
}

__device__ __forceinline__ float block_reduce(float v, float* wsum) {
    const int tid = threadIdx.x;
    #pragma unroll
    for (int o = 16; o > 0; o >>= 1)
        v += __shfl_xor_sync(0xFFFFFFFFu, v, o);
    if ((tid & 31) == 0) wsum[tid >> 5] = v;
    __syncthreads();
    v = 0.0f;
    if (tid < 32) {
        v = (tid < NTHREADS / 32) ? wsum[tid] : 0.0f;
        #pragma unroll
        for (int o = 4; o > 0; o >>= 1)
            v += __shfl_xor_sync(0xFFFFFFFFu, v, o);
    }
    return v;  // valid in tid 0
}

// One-thread TMA bulk prefetch of a tile (p + t) into stage buffer.
__device__ __forceinline__ void prefetch_tile(int tile, uint32_t s_stage,
                                              uint32_t s_mbar,
                                              const float* __restrict__ predict,
                                              const float* __restrict__ target) {
    if (tile < NTILES) {
        asm volatile("mbarrier.arrive.expect_tx.shared.b64 _, [%0], %1;"
                     :: "r"(s_mbar), "r"((uint32_t)STAGE_BYTES) : "memory");
        const char* gp = (const char*)predict + (size_t)tile * TILE_BYTES;
        const char* gt = (const char*)target  + (size_t)tile * TILE_BYTES;
        asm volatile("cp.async.bulk.shared::cta.global.mbarrier::complete_tx::bytes "
                     "[%0], [%1], %2, [%3];"
                     :: "r"(s_stage), "l"(gp), "r"((uint32_t)TILE_BYTES), "r"(s_mbar)
                     : "memory");
        asm volatile("cp.async.bulk.shared::cta.global.mbarrier::complete_tx::bytes "
                     "[%0], [%1], %2, [%3];"
                     :: "r"(s_stage + TILE_BYTES), "l"(gt),
                        "r"((uint32_t)TILE_BYTES), "r"(s_mbar)
                     : "memory");
    }
}

__device__ __forceinline__ void mbar_wait(uint32_t s_mbar, uint32_t phase) {
    asm volatile(
        "{\n\t"
        ".reg .pred P;\n\t"
        "WAIT_%=:\n\t"
        "mbarrier.try_wait.parity.acquire.cta.shared::cta.b64 P, [%0], %1, 0x989680;\n\t"
        "@P bra.uni DONE_%=;\n\t"
        "bra.uni WAIT_%=;\n\t"
        "DONE_%=:\n\t"
        "}"
        :: "r"(s_mbar), "r"(phase) : "memory");
}

__global__ __launch_bounds__(NTHREADS)
void yolo_loss_kernel(const float* __restrict__ predict,
                      const float* __restrict__ target,
                      float* __restrict__ out, int out_size) {
    extern __shared__ float smem[];   // [NSTAGES * STAGE_FLOATS]
    __shared__ __align__(8) uint64_t mbar[NSTAGES];
    __shared__ float wsum[NTHREADS / 32];
    __shared__ int s_is_last;

    const int tid = threadIdx.x;
    const uint32_t s_base = (uint32_t)__cvta_generic_to_shared(smem);
    const uint32_t s_mbar0 = (uint32_t)__cvta_generic_to_shared(mbar);

    // Init mbarriers (count=1: the expect_tx arrive), then fence for async proxy.
    if (tid == 0) {
        #pragma unroll
        for (int s = 0; s < NSTAGES; s++)
            asm volatile("mbarrier.init.shared.b64 [%0], 1;"
                         :: "r"(s_mbar0 + s * 8) : "memory");
    }
    asm volatile("fence.proxy.async.shared::cta;" ::: "memory");
    __syncthreads();

    // Prologue: fill all stages.
    if (tid == 0) {
        #pragma unroll
        for (int s = 0; s < NSTAGES; s++)
            prefetch_tile(blockIdx.x + s * GRID, s_base + s * STAGE_BYTES,
                          s_mbar0 + s * 8, predict, target);
    }

    float acc = 0.0f;
    int j = 0;
    for (int tile = blockIdx.x; tile < NTILES; tile += GRID, j++) {
        const int stage = j % NSTAGES;
        const uint32_t phase = (uint32_t)((j / NSTAGES) & 1);
        mbar_wait(s_mbar0 + stage * 8, phase);

        const float* bp = smem + stage * STAGE_FLOATS;
        const float* bt = bp + TILE_FLOATS;

        if (tid < CELLS_PER_TILE) {
            // ---- box half: elements 0..9 of one cell ----
            const float2* P2 = (const float2*)(bp + tid * ELE);
            const float2* T2 = (const float2*)(bt + tid * ELE);
            float p[10], t[10];
            #pragma unroll
            for (int q = 0; q < 5; q++) {
                float2 a = P2[q]; p[2 * q] = a.x; p[2 * q + 1] = a.y;
                float2 b = T2[q]; t[2 * q] = b.x; t[2 * q + 1] = b.y;
            }

            float conf_flag = t[5];
            float coord = (conf_flag > 0.0f) ? 1.0f : 0.0f;
            float noobj = (conf_flag == 0.0f) ? 1.0f : 0.0f;

            float d4a = p[4] - t[4];
            float d4b = p[9] - t[9];
            float noobj_conf = noobj * (d4a * d4a + d4b * d4b);

            float iou00 = iou_fn(p,     t);
            float iou01 = iou_fn(p,     t + 5);
            float iou10 = iou_fn(p + 5, t);
            float iou11 = iou_fn(p + 5, t + 5);

            int bi0 = (iou10 > iou00) ? 1 : 0;   // ties -> 0, matches jnp.argmax
            int bi1 = (iou11 > iou01) ? 1 : 0;
            float best0 = (bi0 == 0 || bi1 == 0) ? 1.0f : 0.0f;
            float best1 = (bi0 == 1 || bi1 == 1) ? 1.0f : 0.0f;
            float resp0 = coord * best0;
            float resp1 = coord * best1;

            float conf_loss = resp0 * d4a * d4a + resp1 * d4b * d4b;

            float c0 = p[0] - t[0], c1 = p[1] - t[1];
            float c5 = p[5] - t[5], c6 = p[6] - t[6];
            float center = resp0 * (c0 * c0 + c1 * c1) + resp1 * (c5 * c5 + c6 * c6);

            float w0 = p[2] - t[2], h0 = p[3] - t[3];
            float w1 = p[7] - t[7], h1 = p[8] - t[8];
            float wh = resp0 * (w0 * w0 + h0 * h0) + resp1 * (w1 * w1 + h1 * h1);

            acc += 5.0f * (center + wh) + conf_loss + 0.5f * noobj_conf;
        } else {
            // ---- class half: elements 10..29 of one cell ----
            const int cell = tid - CELLS_PER_TILE;
            const float* base_p = bp + cell * ELE;
            const float* base_t = bt + cell * ELE;
            float conf_flag = base_t[5];
            float coord = (conf_flag > 0.0f) ? 1.0f : 0.0f;

            const float2* P2 = (const float2*)(base_p + 10);
            const float2* T2 = (const float2*)(base_t + 10);
            float cls = 0.0f;
            #pragma unroll
            for (int q = 0; q < 10; q++) {
                float2 a = P2[q];
                float2 b = T2[q];
                float dx = a.x - b.x;
                float dy = a.y - b.y;
                cls += dx * dx + dy * dy;
            }
            acc += coord * cls;
        }

        __syncthreads();   // everyone done reading this stage
        if (tid == 0)      // refill it
            prefetch_tile(tile + NSTAGES * GRID, s_base + stage * STAGE_BYTES,
                          s_mbar0 + stage * 8, predict, target);
    }

    // Per-block deterministic reduction, then last-block final sum.
    __syncthreads();
    float bsum = block_reduce(acc, wsum);
    if (tid == 0) {
        g_partials[blockIdx.x] = bsum;
        __threadfence();
        unsigned int prev = atomicAdd(&g_count, 1u);
        s_is_last = (prev == GRID - 1) ? 1 : 0;
    }
    __syncthreads();

    if (s_is_last) {
        __threadfence();
        float s = g_partials[tid];
        if (tid + NTHREADS < GRID) s += g_partials[tid + NTHREADS];
        __syncthreads();
        float tot = block_reduce(s, wsum);
        if (tid == 0) {
            out[0] = tot;
            g_count = 0;   // reset for next graph replay
        }
        for (int i = tid + 1; i < out_size; i += NTHREADS) out[i] = 0.0f;
    }
}

extern "C" void kernel_launch(void* const* d_in, const int* in_sizes, int n_in,
                              void* d_out, int out_size) {
    const float* predict = (const float*)d_in[0];
    const float* target  = (const float*)d_in[1];
    float* out = (float*)d_out;

    size_t smem = (size_t)NSTAGES * STAGE_BYTES;   // 92160 B
    cudaFuncSetAttribute(yolo_loss_kernel,
                         cudaFuncAttributeMaxDynamicSharedMemorySize, (int)smem);

    yolo_loss_kernel<<<GRID, NTHREADS, smem>>>(predict, target, out, out_size);
}